// round 1
// baseline (speedup 1.0000x reference)
#include <cuda_runtime.h>
#include <math_constants.h>

#define BB 2
#define TT 2048
#define EE 768
#define HH 12
#define HD 64
#define BH (BB*HH)
#define MM (BB*TT)
#define ROT 32
#define QSCALE 0.125f   // 64^-0.5

// Scratch (static device allocations are allowed; cudaMalloc is not)
__device__ float g_q[BH * TT * HD];
__device__ float g_k[BH * TT * HD];
__device__ float g_v[BH * TT * HD];
__device__ float g_ctx[BH * TT * HD];

// ---------------------------------------------------------------------------
// QKV projection: C = X @ W^T (both row-major, K-contiguous), epilogue writes
// into [bh][t][d] layout. blockIdx.z selects q/k/v.
// 64x64 tile, K-step 16, 256 threads, 4x4 register tile per thread.
// ---------------------------------------------------------------------------
__global__ __launch_bounds__(256)
void qkv_gemm_kernel(const float* __restrict__ X,
                     const float* __restrict__ Wq,
                     const float* __restrict__ Wk,
                     const float* __restrict__ Wv)
{
    const int which = blockIdx.z;
    const float* Wt = (which == 0) ? Wq : (which == 1) ? Wk : Wv;
    float* dst      = (which == 0) ? g_q : (which == 1) ? g_k : g_v;
    const float scale = (which == 0) ? QSCALE : 1.0f;

    __shared__ float As[16][68];   // [k][m], pitch 68 keeps 16B alignment
    __shared__ float Bs[16][68];   // [k][n]

    const int m0 = blockIdx.x * 64;
    const int n0 = blockIdx.y * 64;
    const int tid = threadIdx.x;
    const int ty = tid >> 4, tx = tid & 15;
    const int lr = tid >> 2;          // load row 0..63
    const int lc = (tid & 3) * 4;     // load k-offset 0,4,8,12

    float acc[4][4] = {};

    for (int k0 = 0; k0 < EE; k0 += 16) {
        float4 a = *(const float4*)(X  + (m0 + lr) * EE + k0 + lc);
        float4 b = *(const float4*)(Wt + (n0 + lr) * EE + k0 + lc);
        As[lc + 0][lr] = a.x; As[lc + 1][lr] = a.y;
        As[lc + 2][lr] = a.z; As[lc + 3][lr] = a.w;
        Bs[lc + 0][lr] = b.x; Bs[lc + 1][lr] = b.y;
        Bs[lc + 2][lr] = b.z; Bs[lc + 3][lr] = b.w;
        __syncthreads();
        #pragma unroll
        for (int kk = 0; kk < 16; kk++) {
            float4 av = *(const float4*)&As[kk][ty * 4];
            float4 bv = *(const float4*)&Bs[kk][tx * 4];
            float ar[4] = {av.x, av.y, av.z, av.w};
            float br[4] = {bv.x, bv.y, bv.z, bv.w};
            #pragma unroll
            for (int i = 0; i < 4; i++)
                #pragma unroll
                for (int j = 0; j < 4; j++)
                    acc[i][j] = fmaf(ar[i], br[j], acc[i][j]);
        }
        __syncthreads();
    }

    // epilogue: write into [b*H+h][t][d]
    const int h  = n0 >> 6;          // n0 multiple of 64, tx*4+j < 64
    const int dd = tx * 4;
    #pragma unroll
    for (int i = 0; i < 4; i++) {
        int m = m0 + ty * 4 + i;
        int b_ = m >> 11;            // /T
        int t  = m & (TT - 1);
        float4 o;
        o.x = acc[i][0] * scale; o.y = acc[i][1] * scale;
        o.z = acc[i][2] * scale; o.w = acc[i][3] * scale;
        *(float4*)(dst + (((size_t)(b_ * HH + h)) * TT + t) * HD + dd) = o;
    }
}

// ---------------------------------------------------------------------------
// RoPE on first 32 dims of each 64-dim head, applied to q, k, AND v.
// new[d]    = x[d]*cos(f[d])    - x[d+16]*sin(f[d])      for d in [0,16)
// new[d+16] = x[d+16]*cos(f[d+16]) + x[d]*sin(f[d+16])
// ---------------------------------------------------------------------------
__global__ __launch_bounds__(256)
void rope_kernel(const float* __restrict__ freqs)
{
    int idx = blockIdx.x * blockDim.x + threadIdx.x;
    const int total = 3 * BH * TT * 16;
    if (idx >= total) return;
    int d = idx & 15;
    int rest = idx >> 4;
    int t = rest & (TT - 1);
    int bha = rest >> 11;
    int bh = bha % BH;
    int a = bha / BH;
    float* s = ((a == 0) ? g_q : (a == 1) ? g_k : g_v) + ((size_t)bh * TT + t) * HD;
    float f1 = freqs[t * ROT + d];
    float f2 = freqs[t * ROT + d + 16];
    float x1 = s[d], x2 = s[d + 16];
    s[d]      = x1 * cosf(f1) - x2 * sinf(f1);
    s[d + 16] = x2 * cosf(f2) + x1 * sinf(f2);
}

// ---------------------------------------------------------------------------
// Flash attention: one CTA = (head, 64-query tile). 64-key tiles, online
// softmax. 256 threads, thread (ty,tx) owns 4 q-rows x 4 cols.
// Dynamic smem: Qt[64][64] (k-major), Kt[64][64] (k-major), Vs[64][64]
// (key-major), Ps[64][64] (row-major) = 64 KB.
// ---------------------------------------------------------------------------
__global__ __launch_bounds__(256)
void attn_kernel()
{
    extern __shared__ float sm[];
    float* Qt = sm;                 // Qt[k*64 + row]
    float* Kt = Qt + 64 * 64;       // Kt[k*64 + col]
    float* Vs = Kt + 64 * 64;       // Vs[key*64 + d]
    float* Ps = Vs + 64 * 64;       // Ps[row*64 + key]

    const int bh = blockIdx.y;
    const int m0 = blockIdx.x * 64;
    const int tid = threadIdx.x;
    const int ty = tid >> 4, tx = tid & 15;

    const float* qbase = g_q + (size_t)bh * TT * HD;
    const float* kbase = g_k + (size_t)bh * TT * HD;
    const float* vbase = g_v + (size_t)bh * TT * HD;

    // Load Q tile transposed into Qt
    #pragma unroll
    for (int it = 0; it < 4; it++) {
        int r = (tid + it * 256) >> 4;
        int c = ((tid + it * 256) & 15) * 4;
        float4 qv = *(const float4*)(qbase + (m0 + r) * HD + c);
        Qt[(c + 0) * 64 + r] = qv.x; Qt[(c + 1) * 64 + r] = qv.y;
        Qt[(c + 2) * 64 + r] = qv.z; Qt[(c + 3) * 64 + r] = qv.w;
    }

    float m_i[4], l_i[4], O[4][4];
    #pragma unroll
    for (int i = 0; i < 4; i++) {
        m_i[i] = -CUDART_INF_F;
        l_i[i] = 0.0f;
        #pragma unroll
        for (int j = 0; j < 4; j++) O[i][j] = 0.0f;
    }

    for (int n0 = 0; n0 < TT; n0 += 64) {
        // load K (transposed) and V tiles
        #pragma unroll
        for (int it = 0; it < 4; it++) {
            int r = (tid + it * 256) >> 4;
            int c = ((tid + it * 256) & 15) * 4;
            float4 kv = *(const float4*)(kbase + (n0 + r) * HD + c);
            Kt[(c + 0) * 64 + r] = kv.x; Kt[(c + 1) * 64 + r] = kv.y;
            Kt[(c + 2) * 64 + r] = kv.z; Kt[(c + 3) * 64 + r] = kv.w;
            float4 vv = *(const float4*)(vbase + (n0 + r) * HD + c);
            *(float4*)&Vs[r * 64 + c] = vv;
        }
        __syncthreads();   // K/V (and Q on first iter) visible

        // S = Q @ K^T for the 4x4 sub-tile
        float s[4][4] = {};
        #pragma unroll
        for (int kk = 0; kk < 64; kk++) {
            float4 av = *(const float4*)&Qt[kk * 64 + ty * 4];
            float4 bv = *(const float4*)&Kt[kk * 64 + tx * 4];
            float ar[4] = {av.x, av.y, av.z, av.w};
            float br[4] = {bv.x, bv.y, bv.z, bv.w};
            #pragma unroll
            for (int i = 0; i < 4; i++)
                #pragma unroll
                for (int j = 0; j < 4; j++)
                    s[i][j] = fmaf(ar[i], br[j], s[i][j]);
        }

        // online softmax: row max over 64 cols (4 local + 16-lane shuffle)
        float mnew[4], alpha[4], rsum[4];
        #pragma unroll
        for (int i = 0; i < 4; i++) {
            float rm = fmaxf(fmaxf(s[i][0], s[i][1]), fmaxf(s[i][2], s[i][3]));
            #pragma unroll
            for (int off = 1; off < 16; off <<= 1)
                rm = fmaxf(rm, __shfl_xor_sync(0xffffffffu, rm, off));
            mnew[i]  = fmaxf(m_i[i], rm);
            alpha[i] = __expf(m_i[i] - mnew[i]);
            float p0 = __expf(s[i][0] - mnew[i]);
            float p1 = __expf(s[i][1] - mnew[i]);
            float p2 = __expf(s[i][2] - mnew[i]);
            float p3 = __expf(s[i][3] - mnew[i]);
            float4 pv; pv.x = p0; pv.y = p1; pv.z = p2; pv.w = p3;
            *(float4*)&Ps[(ty * 4 + i) * 64 + tx * 4] = pv;
            float rs = p0 + p1 + p2 + p3;
            #pragma unroll
            for (int off = 1; off < 16; off <<= 1)
                rs += __shfl_xor_sync(0xffffffffu, rs, off);
            rsum[i] = rs;
            l_i[i] = l_i[i] * alpha[i] + rs;
            m_i[i] = mnew[i];
        }
        __syncthreads();   // Ps visible

        // O = O*alpha + P @ V
        #pragma unroll
        for (int i = 0; i < 4; i++)
            #pragma unroll
            for (int j = 0; j < 4; j++)
                O[i][j] *= alpha[i];
        #pragma unroll
        for (int key = 0; key < 64; key++) {
            float4 vv = *(const float4*)&Vs[key * 64 + tx * 4];
            float vr[4] = {vv.x, vv.y, vv.z, vv.w};
            #pragma unroll
            for (int i = 0; i < 4; i++) {
                float p = Ps[(ty * 4 + i) * 64 + key];
                #pragma unroll
                for (int j = 0; j < 4; j++)
                    O[i][j] = fmaf(p, vr[j], O[i][j]);
            }
        }
        __syncthreads();   // done reading K/V/P before next tile load
    }

    // normalize and write ctx[bh][t][d]
    #pragma unroll
    for (int i = 0; i < 4; i++) {
        float inv = 1.0f / l_i[i];
        float4 o;
        o.x = O[i][0] * inv; o.y = O[i][1] * inv;
        o.z = O[i][2] * inv; o.w = O[i][3] * inv;
        *(float4*)(g_ctx + ((size_t)bh * TT + m0 + ty * 4 + i) * HD + tx * 4) = o;
    }
}

// ---------------------------------------------------------------------------
// Output projection: out[m][n] = sum_e ctx_gathered[m][e] * Wo[n][e] + bo[n]
// ctx_gathered[b*T+t][h*64+d] = g_ctx[(b*H+h)*T*64 + t*64 + d]
// ---------------------------------------------------------------------------
__global__ __launch_bounds__(256)
void out_gemm_kernel(const float* __restrict__ Wo,
                     const float* __restrict__ bo,
                     float* __restrict__ out)
{
    __shared__ float As[16][68];
    __shared__ float Bs[16][68];

    const int m0 = blockIdx.x * 64;
    const int n0 = blockIdx.y * 64;
    const int tid = threadIdx.x;
    const int ty = tid >> 4, tx = tid & 15;
    const int lr = tid >> 2;
    const int lc = (tid & 3) * 4;

    float acc[4][4] = {};

    const int m_ld = m0 + lr;
    const int b_ld = m_ld >> 11;
    const int t_ld = m_ld & (TT - 1);

    for (int k0 = 0; k0 < EE; k0 += 16) {
        int e = k0 + lc;
        int h = e >> 6, d = e & 63;   // 4 consecutive e stay in same head
        float4 a = *(const float4*)(g_ctx +
                     (((size_t)(b_ld * HH + h)) * TT + t_ld) * HD + d);
        float4 b = *(const float4*)(Wo + (n0 + lr) * EE + e);
        As[lc + 0][lr] = a.x; As[lc + 1][lr] = a.y;
        As[lc + 2][lr] = a.z; As[lc + 3][lr] = a.w;
        Bs[lc + 0][lr] = b.x; Bs[lc + 1][lr] = b.y;
        Bs[lc + 2][lr] = b.z; Bs[lc + 3][lr] = b.w;
        __syncthreads();
        #pragma unroll
        for (int kk = 0; kk < 16; kk++) {
            float4 av = *(const float4*)&As[kk][ty * 4];
            float4 bv = *(const float4*)&Bs[kk][tx * 4];
            float ar[4] = {av.x, av.y, av.z, av.w};
            float br[4] = {bv.x, bv.y, bv.z, bv.w};
            #pragma unroll
            for (int i = 0; i < 4; i++)
                #pragma unroll
                for (int j = 0; j < 4; j++)
                    acc[i][j] = fmaf(ar[i], br[j], acc[i][j]);
        }
        __syncthreads();
    }

    float4 bias = *(const float4*)(bo + n0 + tx * 4);
    float bi[4] = {bias.x, bias.y, bias.z, bias.w};
    #pragma unroll
    for (int i = 0; i < 4; i++) {
        int m = m0 + ty * 4 + i;
        float4 o;
        o.x = acc[i][0] + bi[0]; o.y = acc[i][1] + bi[1];
        o.z = acc[i][2] + bi[2]; o.w = acc[i][3] + bi[3];
        *(float4*)(out + (size_t)m * EE + n0 + tx * 4) = o;
    }
}

// ---------------------------------------------------------------------------
extern "C" void kernel_launch(void* const* d_in, const int* in_sizes, int n_in,
                              void* d_out, int out_size)
{
    const float* hid = (const float*)d_in[0];
    const float* rot = (const float*)d_in[1];
    const float* Wq  = (const float*)d_in[2];
    const float* Wk  = (const float*)d_in[3];
    const float* Wv  = (const float*)d_in[4];
    const float* Wo  = (const float*)d_in[5];
    const float* bo  = (const float*)d_in[6];
    float* out = (float*)d_out;

    // 1) QKV projections (z selects q/k/v)
    dim3 g1(MM / 64, EE / 64, 3);
    qkv_gemm_kernel<<<g1, 256>>>(hid, Wq, Wk, Wv);

    // 2) RoPE on q, k, v
    int nrope = 3 * BH * TT * 16;
    rope_kernel<<<(nrope + 255) / 256, 256>>>(rot);

    // 3) Flash attention
    const int smem = 4 * 64 * 64 * (int)sizeof(float);   // 64 KB
    cudaFuncSetAttribute(attn_kernel,
                         cudaFuncAttributeMaxDynamicSharedMemorySize, smem);
    attn_kernel<<<dim3(TT / 64, BH), 256, smem>>>();

    // 4) Output projection + bias
    out_gemm_kernel<<<dim3(MM / 64, EE / 64), 256>>>(Wo, bo, out);
}

// round 3
// speedup vs baseline: 1.1605x; 1.1605x over previous
#include <cuda_runtime.h>
#include <cuda_bf16.h>
#include <math_constants.h>
#include <cstdint>

#define BB 2
#define TT 2048
#define EE 768
#define HH 12
#define HD 64
#define BH (BB*HH)
#define MM (BB*TT)
#define ROT 32
#define QSCALE 0.125f   // 64^-0.5

// ---------------------------------------------------------------------------
// Scratch (static device allocations are allowed; cudaMalloc is not)
// ---------------------------------------------------------------------------
__device__ float g_q[BH * TT * HD];
__device__ float g_k[BH * TT * HD];
__device__ float g_v[BH * TT * HD];
__device__ float g_ctx[BH * TT * HD];

// split-bf16 copies
__device__ __nv_bfloat16 g_Xhi[MM * EE];
__device__ __nv_bfloat16 g_Xlo[MM * EE];
__device__ __nv_bfloat16 g_Wqhi[EE * EE];
__device__ __nv_bfloat16 g_Wqlo[EE * EE];
__device__ __nv_bfloat16 g_Wkhi[EE * EE];
__device__ __nv_bfloat16 g_Wklo[EE * EE];
__device__ __nv_bfloat16 g_Wvhi[EE * EE];
__device__ __nv_bfloat16 g_Wvlo[EE * EE];
__device__ __nv_bfloat16 g_Wohi[EE * EE];
__device__ __nv_bfloat16 g_Wolo[EE * EE];
__device__ __nv_bfloat16 g_Chi[MM * EE];
__device__ __nv_bfloat16 g_Clo[MM * EE];

// ---------------------------------------------------------------------------
// warp-mma helpers (baseline PTX — works on compute_103 virtual arch)
// ---------------------------------------------------------------------------
__device__ __forceinline__ uint32_t smem_u32(const void* p) {
    uint32_t a;
    asm("{ .reg .u64 t; cvta.to.shared.u64 t, %1; cvt.u32.u64 %0, t; }"
        : "=r"(a) : "l"(p));
    return a;
}

__device__ __forceinline__ void ldmx4(uint32_t* r, uint32_t addr) {
    asm volatile("ldmatrix.sync.aligned.m8n8.x4.shared.b16 {%0,%1,%2,%3}, [%4];"
                 : "=r"(r[0]), "=r"(r[1]), "=r"(r[2]), "=r"(r[3]) : "r"(addr));
}
__device__ __forceinline__ void ldmx2(uint32_t* r, uint32_t addr) {
    asm volatile("ldmatrix.sync.aligned.m8n8.x2.shared.b16 {%0,%1}, [%2];"
                 : "=r"(r[0]), "=r"(r[1]) : "r"(addr));
}
__device__ __forceinline__ void mma_bf16(float* c, const uint32_t* a, const uint32_t* b) {
    asm volatile(
        "mma.sync.aligned.m16n8k16.row.col.f32.bf16.bf16.f32 "
        "{%0,%1,%2,%3}, {%4,%5,%6,%7}, {%8,%9}, {%0,%1,%2,%3};"
        : "+f"(c[0]), "+f"(c[1]), "+f"(c[2]), "+f"(c[3])
        : "r"(a[0]), "r"(a[1]), "r"(a[2]), "r"(a[3]), "r"(b[0]), "r"(b[1]));
}

// ---------------------------------------------------------------------------
// split fp32 -> (hi, lo) bf16.  which: 0=X 1=Wq 2=Wk 3=Wv 4=Wo
// ---------------------------------------------------------------------------
__global__ __launch_bounds__(256)
void split_kernel(const float* __restrict__ src, int which, int n4)
{
    __nv_bfloat16 *hi, *lo;
    switch (which) {
        case 0: hi = g_Xhi;  lo = g_Xlo;  break;
        case 1: hi = g_Wqhi; lo = g_Wqlo; break;
        case 2: hi = g_Wkhi; lo = g_Wklo; break;
        case 3: hi = g_Wvhi; lo = g_Wvlo; break;
        default: hi = g_Wohi; lo = g_Wolo; break;
    }
    int i = blockIdx.x * blockDim.x + threadIdx.x;
    if (i >= n4) return;
    float4 x = *(const float4*)(src + i * 4);
    float xs[4] = {x.x, x.y, x.z, x.w};
    __nv_bfloat16 h[4], l[4];
    #pragma unroll
    for (int j = 0; j < 4; j++) {
        h[j] = __float2bfloat16(xs[j]);
        l[j] = __float2bfloat16(xs[j] - __bfloat162float(h[j]));
    }
    *(uint2*)(hi + i * 4) = *(uint2*)h;
    *(uint2*)(lo + i * 4) = *(uint2*)l;
}

// gather ctx [bh][t][d] -> [m][e] and split
__global__ __launch_bounds__(256)
void split_ctx_kernel()
{
    int i = blockIdx.x * blockDim.x + threadIdx.x;   // over MM*EE/4
    if (i >= MM * EE / 4) return;
    int e = (i * 4) % EE;
    int m = (i * 4) / EE;
    int b = m >> 11, t = m & (TT - 1);
    int h = e >> 6,  d = e & 63;
    float4 x = *(const float4*)(g_ctx + (((size_t)(b * HH + h)) * TT + t) * HD + d);
    float xs[4] = {x.x, x.y, x.z, x.w};
    __nv_bfloat16 hh[4], ll[4];
    #pragma unroll
    for (int j = 0; j < 4; j++) {
        hh[j] = __float2bfloat16(xs[j]);
        ll[j] = __float2bfloat16(xs[j] - __bfloat162float(hh[j]));
    }
    *(uint2*)(g_Chi + i * 4) = *(uint2*)hh;
    *(uint2*)(g_Clo + i * 4) = *(uint2*)ll;
}

// ---------------------------------------------------------------------------
// HMMA split-bf16 GEMM core.
// CTA tile 128(M) x 128(N), K chunk 32, 24 chunks over K=768.
// 8 warps: warp_m = wid&1 (2 x 64 rows), warp_n = wid>>1 (4 x 32 cols).
// Warp tile 64x32 = 4 m-tiles(16) x 4 n-tiles(8).
// smem: per-matrix 128 rows x 32 bf16, pitch 40 bf16 (80 B, 16B-aligned rows).
// ---------------------------------------------------------------------------
#define PITCH 40

struct GemmOut {
    float* dst;
    float scale;
    const float* bias;   // nullptr if none
    int qkv_mode;        // 1: scatter [bh][t][d], 0: dense [m][768]
};

__device__ __forceinline__ void gemm_core_hmma(
    __nv_bfloat16* sAh, __nv_bfloat16* sAl,
    __nv_bfloat16* sBh, __nv_bfloat16* sBl,
    const __nv_bfloat16* __restrict__ Ah, const __nv_bfloat16* __restrict__ Al,
    const __nv_bfloat16* __restrict__ Bh, const __nv_bfloat16* __restrict__ Bl,
    int m0, int n0, const GemmOut& go)
{
    const int tid  = threadIdx.x;
    const int wid  = tid >> 5;
    const int lane = tid & 31;
    const int warp_m = (wid & 1) * 64;
    const int warp_n = (wid >> 1) * 32;

    const uint32_t baseAh = smem_u32(sAh);
    const uint32_t baseAl = smem_u32(sAl);
    const uint32_t baseBh = smem_u32(sBh);
    const uint32_t baseBl = smem_u32(sBl);

    // load indexing: each thread loads 2 consecutive uint4 (16 bf16) per matrix
    const int lr = tid >> 1;            // row 0..127
    const int lq = (tid & 1) * 2;       // quad 0 or 2

    float acc[4][4][4];
    #pragma unroll
    for (int i = 0; i < 4; i++)
        #pragma unroll
        for (int j = 0; j < 4; j++)
            #pragma unroll
            for (int v = 0; v < 4; v++) acc[i][j][v] = 0.0f;

    for (int chunk = 0; chunk < 24; chunk++) {
        const int k0 = chunk * 32;
        // ---- stage 4 x (128 x 32) bf16 tiles ----
        {
            const __nv_bfloat16* gA_h = Ah + (size_t)(m0 + lr) * EE + k0 + lq * 8;
            const __nv_bfloat16* gA_l = Al + (size_t)(m0 + lr) * EE + k0 + lq * 8;
            const __nv_bfloat16* gB_h = Bh + (size_t)(n0 + lr) * EE + k0 + lq * 8;
            const __nv_bfloat16* gB_l = Bl + (size_t)(n0 + lr) * EE + k0 + lq * 8;
            uint4 a0 = *(const uint4*)gA_h;       uint4 a1 = *(const uint4*)(gA_h + 8);
            uint4 b0 = *(const uint4*)gA_l;       uint4 b1 = *(const uint4*)(gA_l + 8);
            uint4 c0 = *(const uint4*)gB_h;       uint4 c1 = *(const uint4*)(gB_h + 8);
            uint4 d0 = *(const uint4*)gB_l;       uint4 d1 = *(const uint4*)(gB_l + 8);
            int so = lr * PITCH + lq * 8;
            *(uint4*)(sAh + so) = a0;  *(uint4*)(sAh + so + 8) = a1;
            *(uint4*)(sAl + so) = b0;  *(uint4*)(sAl + so + 8) = b1;
            *(uint4*)(sBh + so) = c0;  *(uint4*)(sBh + so + 8) = c1;
            *(uint4*)(sBl + so) = d0;  *(uint4*)(sBl + so + 8) = d1;
        }
        __syncthreads();

        #pragma unroll
        for (int ks = 0; ks < 2; ks++) {
            // A fragments (hi & lo) for 4 m-tiles
            uint32_t ah[4][4], al[4][4];
            const int arow = warp_m + (lane & 15);
            const int acol = ks * 16 + (lane >> 4) * 8;
            #pragma unroll
            for (int i = 0; i < 4; i++) {
                uint32_t off = (uint32_t)(((arow + i * 16) * PITCH + acol) * 2);
                ldmx4(ah[i], baseAh + off);
                ldmx4(al[i], baseAl + off);
            }
            // B fragments per n-tile
            const int brow = warp_n + (lane & 7);
            const int bcol = ks * 16 + ((lane >> 3) & 1) * 8;
            #pragma unroll
            for (int j = 0; j < 4; j++) {
                uint32_t boff = (uint32_t)(((brow + j * 8) * PITCH + bcol) * 2);
                uint32_t bh[2], bl[2];
                ldmx2(bh, baseBh + boff);
                ldmx2(bl, baseBl + boff);
                #pragma unroll
                for (int i = 0; i < 4; i++) {
                    mma_bf16(acc[i][j], ah[i], bh);
                    mma_bf16(acc[i][j], ah[i], bl);
                    mma_bf16(acc[i][j], al[i], bh);
                }
            }
        }
        __syncthreads();
    }

    // ---- epilogue: fragment layout row = t/4 (+8), col = 2*(t%4) ----
    const int r0 = m0 + warp_m + (lane >> 2);
    const int c0 = n0 + warp_n + (lane & 3) * 2;
    #pragma unroll
    for (int i = 0; i < 4; i++) {
        #pragma unroll
        for (int j = 0; j < 4; j++) {
            int col = c0 + j * 8;
            #pragma unroll
            for (int half = 0; half < 2; half++) {
                int row = r0 + i * 16 + half * 8;
                float v0 = acc[i][j][half * 2 + 0];
                float v1 = acc[i][j][half * 2 + 1];
                if (go.qkv_mode) {
                    int b = row >> 11, t = row & (TT - 1);
                    int h = col >> 6, d = col & 63;
                    float2 o;
                    o.x = v0 * go.scale; o.y = v1 * go.scale;
                    *(float2*)(go.dst + (((size_t)(b * HH + h)) * TT + t) * HD + d) = o;
                } else {
                    float2 o;
                    o.x = v0 + go.bias[col];
                    o.y = v1 + go.bias[col + 1];
                    *(float2*)(go.dst + (size_t)row * EE + col) = o;
                }
            }
        }
    }
}

__global__ __launch_bounds__(256)
void hmma_gemm_qkv_kernel()
{
    __shared__ __nv_bfloat16 sAh[128 * PITCH], sAl[128 * PITCH];
    __shared__ __nv_bfloat16 sBh[128 * PITCH], sBl[128 * PITCH];
    const int which = blockIdx.z;
    const __nv_bfloat16 *Bh, *Bl;
    GemmOut go; go.bias = nullptr; go.qkv_mode = 1;
    if (which == 0)      { Bh = g_Wqhi; Bl = g_Wqlo; go.dst = g_q; go.scale = QSCALE; }
    else if (which == 1) { Bh = g_Wkhi; Bl = g_Wklo; go.dst = g_k; go.scale = 1.0f; }
    else                 { Bh = g_Wvhi; Bl = g_Wvlo; go.dst = g_v; go.scale = 1.0f; }
    gemm_core_hmma(sAh, sAl, sBh, sBl, g_Xhi, g_Xlo, Bh, Bl,
                   blockIdx.x * 128, blockIdx.y * 128, go);
}

__global__ __launch_bounds__(256)
void hmma_gemm_out_kernel(const float* __restrict__ bo, float* __restrict__ out)
{
    __shared__ __nv_bfloat16 sAh[128 * PITCH], sAl[128 * PITCH];
    __shared__ __nv_bfloat16 sBh[128 * PITCH], sBl[128 * PITCH];
    GemmOut go; go.dst = out; go.scale = 1.0f; go.bias = bo; go.qkv_mode = 0;
    gemm_core_hmma(sAh, sAl, sBh, sBl, g_Chi, g_Clo, g_Wohi, g_Wolo,
                   blockIdx.x * 128, blockIdx.y * 128, go);
}

// ---------------------------------------------------------------------------
// RoPE on first 32 dims of each 64-dim head, applied to q, k, AND v.
// ---------------------------------------------------------------------------
__global__ __launch_bounds__(256)
void rope_kernel(const float* __restrict__ freqs)
{
    int idx = blockIdx.x * blockDim.x + threadIdx.x;
    const int total = 3 * BH * TT * 16;
    if (idx >= total) return;
    int d = idx & 15;
    int rest = idx >> 4;
    int t = rest & (TT - 1);
    int bha = rest >> 11;
    int bh = bha % BH;
    int a = bha / BH;
    float* s = ((a == 0) ? g_q : (a == 1) ? g_k : g_v) + ((size_t)bh * TT + t) * HD;
    float f1 = freqs[t * ROT + d];
    float f2 = freqs[t * ROT + d + 16];
    float x1 = s[d], x2 = s[d + 16];
    s[d]      = x1 * cosf(f1) - x2 * sinf(f1);
    s[d + 16] = x2 * cosf(f2) + x1 * sinf(f2);
}

// ---------------------------------------------------------------------------
// Flash attention (fp32 SIMT — unchanged, correct)
// ---------------------------------------------------------------------------
__global__ __launch_bounds__(256)
void attn_kernel()
{
    extern __shared__ float sm[];
    float* Qt = sm;
    float* Kt = Qt + 64 * 64;
    float* Vs = Kt + 64 * 64;
    float* Ps = Vs + 64 * 64;

    const int bh = blockIdx.y;
    const int m0 = blockIdx.x * 64;
    const int tid = threadIdx.x;
    const int ty = tid >> 4, tx = tid & 15;

    const float* qbase = g_q + (size_t)bh * TT * HD;
    const float* kbase = g_k + (size_t)bh * TT * HD;
    const float* vbase = g_v + (size_t)bh * TT * HD;

    #pragma unroll
    for (int it = 0; it < 4; it++) {
        int r = (tid + it * 256) >> 4;
        int c = ((tid + it * 256) & 15) * 4;
        float4 qv = *(const float4*)(qbase + (m0 + r) * HD + c);
        Qt[(c + 0) * 64 + r] = qv.x; Qt[(c + 1) * 64 + r] = qv.y;
        Qt[(c + 2) * 64 + r] = qv.z; Qt[(c + 3) * 64 + r] = qv.w;
    }

    float m_i[4], l_i[4], O[4][4];
    #pragma unroll
    for (int i = 0; i < 4; i++) {
        m_i[i] = -CUDART_INF_F;
        l_i[i] = 0.0f;
        #pragma unroll
        for (int j = 0; j < 4; j++) O[i][j] = 0.0f;
    }

    for (int n0 = 0; n0 < TT; n0 += 64) {
        #pragma unroll
        for (int it = 0; it < 4; it++) {
            int r = (tid + it * 256) >> 4;
            int c = ((tid + it * 256) & 15) * 4;
            float4 kv = *(const float4*)(kbase + (n0 + r) * HD + c);
            Kt[(c + 0) * 64 + r] = kv.x; Kt[(c + 1) * 64 + r] = kv.y;
            Kt[(c + 2) * 64 + r] = kv.z; Kt[(c + 3) * 64 + r] = kv.w;
            float4 vv = *(const float4*)(vbase + (n0 + r) * HD + c);
            *(float4*)&Vs[r * 64 + c] = vv;
        }
        __syncthreads();

        float s[4][4] = {};
        #pragma unroll
        for (int kk = 0; kk < 64; kk++) {
            float4 av = *(const float4*)&Qt[kk * 64 + ty * 4];
            float4 bv = *(const float4*)&Kt[kk * 64 + tx * 4];
            float ar[4] = {av.x, av.y, av.z, av.w};
            float br[4] = {bv.x, bv.y, bv.z, bv.w};
            #pragma unroll
            for (int i = 0; i < 4; i++)
                #pragma unroll
                for (int j = 0; j < 4; j++)
                    s[i][j] = fmaf(ar[i], br[j], s[i][j]);
        }

        float mnew[4], alpha[4];
        #pragma unroll
        for (int i = 0; i < 4; i++) {
            float rm = fmaxf(fmaxf(s[i][0], s[i][1]), fmaxf(s[i][2], s[i][3]));
            #pragma unroll
            for (int off = 1; off < 16; off <<= 1)
                rm = fmaxf(rm, __shfl_xor_sync(0xffffffffu, rm, off));
            mnew[i]  = fmaxf(m_i[i], rm);
            alpha[i] = __expf(m_i[i] - mnew[i]);
            float p0 = __expf(s[i][0] - mnew[i]);
            float p1 = __expf(s[i][1] - mnew[i]);
            float p2 = __expf(s[i][2] - mnew[i]);
            float p3 = __expf(s[i][3] - mnew[i]);
            float4 pv; pv.x = p0; pv.y = p1; pv.z = p2; pv.w = p3;
            *(float4*)&Ps[(ty * 4 + i) * 64 + tx * 4] = pv;
            float rs = p0 + p1 + p2 + p3;
            #pragma unroll
            for (int off = 1; off < 16; off <<= 1)
                rs += __shfl_xor_sync(0xffffffffu, rs, off);
            l_i[i] = l_i[i] * alpha[i] + rs;
            m_i[i] = mnew[i];
        }
        __syncthreads();

        #pragma unroll
        for (int i = 0; i < 4; i++)
            #pragma unroll
            for (int j = 0; j < 4; j++)
                O[i][j] *= alpha[i];
        #pragma unroll
        for (int key = 0; key < 64; key++) {
            float4 vv = *(const float4*)&Vs[key * 64 + tx * 4];
            float vr[4] = {vv.x, vv.y, vv.z, vv.w};
            #pragma unroll
            for (int i = 0; i < 4; i++) {
                float p = Ps[(ty * 4 + i) * 64 + key];
                #pragma unroll
                for (int j = 0; j < 4; j++)
                    O[i][j] = fmaf(p, vr[j], O[i][j]);
            }
        }
        __syncthreads();
    }

    #pragma unroll
    for (int i = 0; i < 4; i++) {
        float inv = 1.0f / l_i[i];
        float4 o;
        o.x = O[i][0] * inv; o.y = O[i][1] * inv;
        o.z = O[i][2] * inv; o.w = O[i][3] * inv;
        *(float4*)(g_ctx + ((size_t)bh * TT + m0 + ty * 4 + i) * HD + tx * 4) = o;
    }
}

// ---------------------------------------------------------------------------
extern "C" void kernel_launch(void* const* d_in, const int* in_sizes, int n_in,
                              void* d_out, int out_size)
{
    const float* hid = (const float*)d_in[0];
    const float* rot = (const float*)d_in[1];
    const float* Wq  = (const float*)d_in[2];
    const float* Wk  = (const float*)d_in[3];
    const float* Wv  = (const float*)d_in[4];
    const float* Wo  = (const float*)d_in[5];
    const float* bo  = (const float*)d_in[6];
    float* out = (float*)d_out;

    cudaFuncSetAttribute(attn_kernel,
                         cudaFuncAttributeMaxDynamicSharedMemorySize,
                         4 * 64 * 64 * (int)sizeof(float));

    // 1) split inputs / weights into hi/lo bf16
    split_kernel<<<(MM * EE / 4 + 255) / 256, 256>>>(hid, 0, MM * EE / 4);
    split_kernel<<<(EE * EE / 4 + 255) / 256, 256>>>(Wq, 1, EE * EE / 4);
    split_kernel<<<(EE * EE / 4 + 255) / 256, 256>>>(Wk, 2, EE * EE / 4);
    split_kernel<<<(EE * EE / 4 + 255) / 256, 256>>>(Wv, 3, EE * EE / 4);
    split_kernel<<<(EE * EE / 4 + 255) / 256, 256>>>(Wo, 4, EE * EE / 4);

    // 2) QKV projections on tensor cores (z selects q/k/v)
    hmma_gemm_qkv_kernel<<<dim3(MM / 128, EE / 128, 3), 256>>>();

    // 3) RoPE on q, k, v
    int nrope = 3 * BH * TT * 16;
    rope_kernel<<<(nrope + 255) / 256, 256>>>(rot);

    // 4) Flash attention (fp32)
    attn_kernel<<<dim3(TT / 64, BH), 256, 4 * 64 * 64 * sizeof(float)>>>();

    // 5) gather + split ctx, then output projection on tensor cores
    split_ctx_kernel<<<(MM * EE / 4 + 255) / 256, 256>>>();
    hmma_gemm_out_kernel<<<dim3(MM / 128, EE / 128), 256>>>(bo, out);
}

// round 4
// speedup vs baseline: 2.4657x; 2.1247x over previous
#include <cuda_runtime.h>
#include <cuda_bf16.h>
#include <math_constants.h>
#include <cstdint>

#define BB 2
#define TT 2048
#define EE 768
#define HH 12
#define HD 64
#define BH (BB*HH)
#define MM (BB*TT)
#define ROT 32
#define QSCALE 0.125f   // 64^-0.5

// ---------------------------------------------------------------------------
// Scratch
// ---------------------------------------------------------------------------
__device__ float g_q[BH * TT * HD];
__device__ float g_k[BH * TT * HD];
__device__ float g_v[BH * TT * HD];
__device__ float g_ctx[BH * TT * HD];

__device__ __nv_bfloat16 g_Xhi[MM * EE];
__device__ __nv_bfloat16 g_Xlo[MM * EE];
__device__ __nv_bfloat16 g_Wqhi[EE * EE];
__device__ __nv_bfloat16 g_Wqlo[EE * EE];
__device__ __nv_bfloat16 g_Wkhi[EE * EE];
__device__ __nv_bfloat16 g_Wklo[EE * EE];
__device__ __nv_bfloat16 g_Wvhi[EE * EE];
__device__ __nv_bfloat16 g_Wvlo[EE * EE];
__device__ __nv_bfloat16 g_Wohi[EE * EE];
__device__ __nv_bfloat16 g_Wolo[EE * EE];
__device__ __nv_bfloat16 g_Chi[MM * EE];
__device__ __nv_bfloat16 g_Clo[MM * EE];

// post-RoPE split q/k/v
__device__ __nv_bfloat16 g_qhi[BH * TT * HD];
__device__ __nv_bfloat16 g_qlo[BH * TT * HD];
__device__ __nv_bfloat16 g_khi[BH * TT * HD];
__device__ __nv_bfloat16 g_klo[BH * TT * HD];
__device__ __nv_bfloat16 g_vhi[BH * TT * HD];
__device__ __nv_bfloat16 g_vlo[BH * TT * HD];

// ---------------------------------------------------------------------------
// PTX helpers (baseline, compile for compute_103)
// ---------------------------------------------------------------------------
__device__ __forceinline__ uint32_t smem_u32(const void* p) {
    uint32_t a;
    asm("{ .reg .u64 t; cvta.to.shared.u64 t, %1; cvt.u32.u64 %0, t; }"
        : "=r"(a) : "l"(p));
    return a;
}
__device__ __forceinline__ void ldmx4(uint32_t* r, uint32_t addr) {
    asm volatile("ldmatrix.sync.aligned.m8n8.x4.shared.b16 {%0,%1,%2,%3}, [%4];"
                 : "=r"(r[0]), "=r"(r[1]), "=r"(r[2]), "=r"(r[3]) : "r"(addr));
}
__device__ __forceinline__ void ldmx2(uint32_t* r, uint32_t addr) {
    asm volatile("ldmatrix.sync.aligned.m8n8.x2.shared.b16 {%0,%1}, [%2];"
                 : "=r"(r[0]), "=r"(r[1]) : "r"(addr));
}
__device__ __forceinline__ void ldmx2t(uint32_t* r, uint32_t addr) {
    asm volatile("ldmatrix.sync.aligned.m8n8.x2.trans.shared.b16 {%0,%1}, [%2];"
                 : "=r"(r[0]), "=r"(r[1]) : "r"(addr));
}
__device__ __forceinline__ void mma_bf16(float* c, const uint32_t* a, const uint32_t* b) {
    asm volatile(
        "mma.sync.aligned.m16n8k16.row.col.f32.bf16.bf16.f32 "
        "{%0,%1,%2,%3}, {%4,%5,%6,%7}, {%8,%9}, {%0,%1,%2,%3};"
        : "+f"(c[0]), "+f"(c[1]), "+f"(c[2]), "+f"(c[3])
        : "r"(a[0]), "r"(a[1]), "r"(a[2]), "r"(a[3]), "r"(b[0]), "r"(b[1]));
}
__device__ __forceinline__ void cp16(uint32_t saddr, const void* g) {
    asm volatile("cp.async.cg.shared.global [%0], [%1], 16;" :: "r"(saddr), "l"(g));
}

// MUFU-free exp: e^x = 2^(x*log2e), args must be <= ~0 (clamped at -87)
__device__ __forceinline__ float exp_fma(float x) {
    x = fmaxf(x, -87.0f);
    float t = x * 1.4426950408889634f;
    float r = t + 12582912.0f;             // round-to-nearest-int magic
    float fi = r - 12582912.0f;
    float f = t - fi;                      // f in [-0.5, 0.5]
    float p = 1.3333558146428443e-3f;
    p = fmaf(p, f, 9.618129842071803e-3f);
    p = fmaf(p, f, 5.550410866482158e-2f);
    p = fmaf(p, f, 2.402265069591007e-1f);
    p = fmaf(p, f, 6.931471805599453e-1f);
    p = fmaf(p, f, 1.0f);
    int ii = __float_as_int(r) - 0x4B400000;
    float sc = __int_as_float((127 + ii) << 23);
    return p * sc;
}
__device__ __forceinline__ uint32_t pack_bf16(float a, float b) {
    __nv_bfloat162 h = __floats2bfloat162_rn(a, b);
    return *(uint32_t*)&h;
}

// ---------------------------------------------------------------------------
// split fp32 -> (hi, lo) bf16.  which: 0=X 1=Wq 2=Wk 3=Wv 4=Wo
// ---------------------------------------------------------------------------
__global__ __launch_bounds__(256)
void split_kernel(const float* __restrict__ src, int which, int n4)
{
    __nv_bfloat16 *hi, *lo;
    switch (which) {
        case 0: hi = g_Xhi;  lo = g_Xlo;  break;
        case 1: hi = g_Wqhi; lo = g_Wqlo; break;
        case 2: hi = g_Wkhi; lo = g_Wklo; break;
        case 3: hi = g_Wvhi; lo = g_Wvlo; break;
        default: hi = g_Wohi; lo = g_Wolo; break;
    }
    int i = blockIdx.x * blockDim.x + threadIdx.x;
    if (i >= n4) return;
    float4 x = *(const float4*)(src + i * 4);
    float xs[4] = {x.x, x.y, x.z, x.w};
    __nv_bfloat16 h[4], l[4];
    #pragma unroll
    for (int j = 0; j < 4; j++) {
        h[j] = __float2bfloat16(xs[j]);
        l[j] = __float2bfloat16(xs[j] - __bfloat162float(h[j]));
    }
    *(uint2*)(hi + i * 4) = *(uint2*)h;
    *(uint2*)(lo + i * 4) = *(uint2*)l;
}

__global__ __launch_bounds__(256)
void split_ctx_kernel()
{
    int i = blockIdx.x * blockDim.x + threadIdx.x;
    if (i >= MM * EE / 4) return;
    int e = (i * 4) % EE;
    int m = (i * 4) / EE;
    int b = m >> 11, t = m & (TT - 1);
    int h = e >> 6,  d = e & 63;
    float4 x = *(const float4*)(g_ctx + (((size_t)(b * HH + h)) * TT + t) * HD + d);
    float xs[4] = {x.x, x.y, x.z, x.w};
    __nv_bfloat16 hh[4], ll[4];
    #pragma unroll
    for (int j = 0; j < 4; j++) {
        hh[j] = __float2bfloat16(xs[j]);
        ll[j] = __float2bfloat16(xs[j] - __bfloat162float(hh[j]));
    }
    *(uint2*)(g_Chi + i * 4) = *(uint2*)hh;
    *(uint2*)(g_Clo + i * 4) = *(uint2*)ll;
}

// ---------------------------------------------------------------------------
// RoPE (cos/sin on first 32 dims) + hi/lo split of q, k, v
// thread handles (a, bh, t, d) with d in [0,16): dims d, d+16 (rope), d+32, d+48
// ---------------------------------------------------------------------------
__global__ __launch_bounds__(256)
void rope_split_kernel(const float* __restrict__ freqs)
{
    int idx = blockIdx.x * blockDim.x + threadIdx.x;
    const int total = 3 * BH * TT * 16;
    if (idx >= total) return;
    int d = idx & 15;
    int rest = idx >> 4;
    int t = rest & (TT - 1);
    int bha = rest >> 11;
    int bh = bha % BH;
    int a = bha / BH;
    const float* s = ((a == 0) ? g_q : (a == 1) ? g_k : g_v) + ((size_t)bh * TT + t) * HD;
    __nv_bfloat16* hi = ((a == 0) ? g_qhi : (a == 1) ? g_khi : g_vhi) + ((size_t)bh * TT + t) * HD;
    __nv_bfloat16* lo = ((a == 0) ? g_qlo : (a == 1) ? g_klo : g_vlo) + ((size_t)bh * TT + t) * HD;

    float f1 = freqs[t * ROT + d];
    float f2 = freqs[t * ROT + d + 16];
    float x1 = s[d], x2 = s[d + 16];
    float vals[4];
    vals[0] = x1 * cosf(f1) - x2 * sinf(f1);
    vals[1] = x2 * cosf(f2) + x1 * sinf(f2);
    vals[2] = s[d + 32];
    vals[3] = s[d + 48];
    int ds[4] = {d, d + 16, d + 32, d + 48};
    #pragma unroll
    for (int j = 0; j < 4; j++) {
        __nv_bfloat16 h = __float2bfloat16(vals[j]);
        hi[ds[j]] = h;
        lo[ds[j]] = __float2bfloat16(vals[j] - __bfloat162float(h));
    }
}

// ---------------------------------------------------------------------------
// HMMA projection GEMM (unchanged from R2)
// ---------------------------------------------------------------------------
#define PITCH 40

struct GemmOut {
    float* dst;
    float scale;
    const float* bias;
    int qkv_mode;
};

__device__ __forceinline__ void gemm_core_hmma(
    __nv_bfloat16* sAh, __nv_bfloat16* sAl,
    __nv_bfloat16* sBh, __nv_bfloat16* sBl,
    const __nv_bfloat16* __restrict__ Ah, const __nv_bfloat16* __restrict__ Al,
    const __nv_bfloat16* __restrict__ Bh, const __nv_bfloat16* __restrict__ Bl,
    int m0, int n0, const GemmOut& go)
{
    const int tid  = threadIdx.x;
    const int wid  = tid >> 5;
    const int lane = tid & 31;
    const int warp_m = (wid & 1) * 64;
    const int warp_n = (wid >> 1) * 32;

    const uint32_t baseAh = smem_u32(sAh);
    const uint32_t baseAl = smem_u32(sAl);
    const uint32_t baseBh = smem_u32(sBh);
    const uint32_t baseBl = smem_u32(sBl);

    const int lr = tid >> 1;
    const int lq = (tid & 1) * 2;

    float acc[4][4][4];
    #pragma unroll
    for (int i = 0; i < 4; i++)
        #pragma unroll
        for (int j = 0; j < 4; j++)
            #pragma unroll
            for (int v = 0; v < 4; v++) acc[i][j][v] = 0.0f;

    for (int chunk = 0; chunk < 24; chunk++) {
        const int k0 = chunk * 32;
        {
            const __nv_bfloat16* gA_h = Ah + (size_t)(m0 + lr) * EE + k0 + lq * 8;
            const __nv_bfloat16* gA_l = Al + (size_t)(m0 + lr) * EE + k0 + lq * 8;
            const __nv_bfloat16* gB_h = Bh + (size_t)(n0 + lr) * EE + k0 + lq * 8;
            const __nv_bfloat16* gB_l = Bl + (size_t)(n0 + lr) * EE + k0 + lq * 8;
            uint4 a0 = *(const uint4*)gA_h;  uint4 a1 = *(const uint4*)(gA_h + 8);
            uint4 b0 = *(const uint4*)gA_l;  uint4 b1 = *(const uint4*)(gA_l + 8);
            uint4 c0 = *(const uint4*)gB_h;  uint4 c1 = *(const uint4*)(gB_h + 8);
            uint4 d0 = *(const uint4*)gB_l;  uint4 d1 = *(const uint4*)(gB_l + 8);
            int so = lr * PITCH + lq * 8;
            *(uint4*)(sAh + so) = a0;  *(uint4*)(sAh + so + 8) = a1;
            *(uint4*)(sAl + so) = b0;  *(uint4*)(sAl + so + 8) = b1;
            *(uint4*)(sBh + so) = c0;  *(uint4*)(sBh + so + 8) = c1;
            *(uint4*)(sBl + so) = d0;  *(uint4*)(sBl + so + 8) = d1;
        }
        __syncthreads();

        #pragma unroll
        for (int ks = 0; ks < 2; ks++) {
            uint32_t ah[4][4], al[4][4];
            const int arow = warp_m + (lane & 15);
            const int acol = ks * 16 + (lane >> 4) * 8;
            #pragma unroll
            for (int i = 0; i < 4; i++) {
                uint32_t off = (uint32_t)(((arow + i * 16) * PITCH + acol) * 2);
                ldmx4(ah[i], baseAh + off);
                ldmx4(al[i], baseAl + off);
            }
            const int brow = warp_n + (lane & 7);
            const int bcol = ks * 16 + ((lane >> 3) & 1) * 8;
            #pragma unroll
            for (int j = 0; j < 4; j++) {
                uint32_t boff = (uint32_t)(((brow + j * 8) * PITCH + bcol) * 2);
                uint32_t bh[2], bl[2];
                ldmx2(bh, baseBh + boff);
                ldmx2(bl, baseBl + boff);
                #pragma unroll
                for (int i = 0; i < 4; i++) {
                    mma_bf16(acc[i][j], ah[i], bh);
                    mma_bf16(acc[i][j], ah[i], bl);
                    mma_bf16(acc[i][j], al[i], bh);
                }
            }
        }
        __syncthreads();
    }

    const int r0 = m0 + warp_m + (lane >> 2);
    const int c0 = n0 + warp_n + (lane & 3) * 2;
    #pragma unroll
    for (int i = 0; i < 4; i++) {
        #pragma unroll
        for (int j = 0; j < 4; j++) {
            int col = c0 + j * 8;
            #pragma unroll
            for (int half = 0; half < 2; half++) {
                int row = r0 + i * 16 + half * 8;
                float v0 = acc[i][j][half * 2 + 0];
                float v1 = acc[i][j][half * 2 + 1];
                if (go.qkv_mode) {
                    int b = row >> 11, t = row & (TT - 1);
                    int h = col >> 6, d = col & 63;
                    float2 o;
                    o.x = v0 * go.scale; o.y = v1 * go.scale;
                    *(float2*)(go.dst + (((size_t)(b * HH + h)) * TT + t) * HD + d) = o;
                } else {
                    float2 o;
                    o.x = v0 + go.bias[col];
                    o.y = v1 + go.bias[col + 1];
                    *(float2*)(go.dst + (size_t)row * EE + col) = o;
                }
            }
        }
    }
}

__global__ __launch_bounds__(256)
void hmma_gemm_qkv_kernel()
{
    __shared__ __nv_bfloat16 sAh[128 * PITCH], sAl[128 * PITCH];
    __shared__ __nv_bfloat16 sBh[128 * PITCH], sBl[128 * PITCH];
    const int which = blockIdx.z;
    const __nv_bfloat16 *Bh, *Bl;
    GemmOut go; go.bias = nullptr; go.qkv_mode = 1;
    if (which == 0)      { Bh = g_Wqhi; Bl = g_Wqlo; go.dst = g_q; go.scale = QSCALE; }
    else if (which == 1) { Bh = g_Wkhi; Bl = g_Wklo; go.dst = g_k; go.scale = 1.0f; }
    else                 { Bh = g_Wvhi; Bl = g_Wvlo; go.dst = g_v; go.scale = 1.0f; }
    gemm_core_hmma(sAh, sAl, sBh, sBl, g_Xhi, g_Xlo, Bh, Bl,
                   blockIdx.x * 128, blockIdx.y * 128, go);
}

__global__ __launch_bounds__(256)
void hmma_gemm_out_kernel(const float* __restrict__ bo, float* __restrict__ out)
{
    __shared__ __nv_bfloat16 sAh[128 * PITCH], sAl[128 * PITCH];
    __shared__ __nv_bfloat16 sBh[128 * PITCH], sBl[128 * PITCH];
    GemmOut go; go.dst = out; go.scale = 1.0f; go.bias = bo; go.qkv_mode = 0;
    gemm_core_hmma(sAh, sAl, sBh, sBl, g_Chi, g_Clo, g_Wohi, g_Wolo,
                   blockIdx.x * 128, blockIdx.y * 128, go);
}

// ---------------------------------------------------------------------------
// HMMA flash attention.
// CTA: 128 q-rows of one head; 8 warps x 16 rows. K-tile = 64 keys,
// double-buffered via cp.async. Split-bf16 for QK^T and PV.
// smem: 2 stages x {Khi,Klo,Vhi,Vlo} 64x72bf16 each (pitch 144B) = 73728 B.
// Q staged once at start in stage-0 area.
// ---------------------------------------------------------------------------
#define AP 144                 // row pitch in bytes (72 bf16)
#define MAT_B (64 * AP)        // 9216
#define STAGE_B (4 * MAT_B)    // 36864
#define ATTN_SMEM (2 * STAGE_B)

__device__ __forceinline__ void stage_kv(uint32_t sb,
    const char* kh, const char* kl, const char* vh, const char* vl,
    int n0, int tid)
{
    #pragma unroll
    for (int m = 0; m < 4; m++) {
        const char* src = (m == 0) ? kh : (m == 1) ? kl : (m == 2) ? vh : vl;
        #pragma unroll
        for (int it = 0; it < 2; it++) {
            int i = tid + it * 256;          // 0..511
            int r = i >> 3, c = (i & 7) * 16;
            cp16(sb + (uint32_t)(m * MAT_B + r * AP + c),
                 src + (size_t)(n0 + r) * 128 + c);
        }
    }
}

__global__ __launch_bounds__(256)
void attn_hmma_kernel()
{
    extern __shared__ char dsm[];
    const int bh  = blockIdx.y;
    const int m0  = blockIdx.x * 128;
    const int tid = threadIdx.x;
    const int wid = tid >> 5, lane = tid & 31;
    const int wm  = wid * 16;

    const size_t hb = (size_t)bh * TT * HD;
    const char* qh_g = (const char*)(g_qhi + hb);
    const char* ql_g = (const char*)(g_qlo + hb);
    const char* kh_g = (const char*)(g_khi + hb);
    const char* kl_g = (const char*)(g_klo + hb);
    const char* vh_g = (const char*)(g_vhi + hb);
    const char* vl_g = (const char*)(g_vlo + hb);

    const uint32_t sbase = smem_u32(dsm);

    // ---- stage Q hi (offset 0) and Q lo (offset 18432), pitch 144 ----
    #pragma unroll
    for (int it = 0; it < 4; it++) {
        int i = tid + it * 256;              // 0..1023
        int r = i >> 3, c = (i & 7) * 16;
        *(uint4*)(dsm + r * AP + c) =
            *(const uint4*)(qh_g + (size_t)(m0 + r) * 128 + c);
        *(uint4*)(dsm + 18432 + r * AP + c) =
            *(const uint4*)(ql_g + (size_t)(m0 + r) * 128 + c);
    }
    __syncthreads();

    uint32_t qh[4][4], ql[4][4];
    #pragma unroll
    for (int kt = 0; kt < 4; kt++) {
        uint32_t off = (uint32_t)((wm + (lane & 15)) * AP + kt * 32 + (lane >> 4) * 16);
        ldmx4(qh[kt], sbase + off);
        ldmx4(ql[kt], sbase + 18432 + off);
    }
    __syncthreads();

    float O[8][4];
    #pragma unroll
    for (int j = 0; j < 8; j++)
        #pragma unroll
        for (int v = 0; v < 4; v++) O[j][v] = 0.0f;
    float miA = -CUDART_INF_F, miB = -CUDART_INF_F;
    float liA = 0.0f, liB = 0.0f;

    // prefetch tile 0 into buf 0
    stage_kv(sbase, kh_g, kl_g, vh_g, vl_g, 0, tid);
    asm volatile("cp.async.commit_group;");

    for (int t = 0; t < TT / 64; t++) {
        if (t + 1 < TT / 64)
            stage_kv(sbase + ((t + 1) & 1) * STAGE_B,
                     kh_g, kl_g, vh_g, vl_g, (t + 1) * 64, tid);
        asm volatile("cp.async.commit_group;");
        asm volatile("cp.async.wait_group 1;");
        __syncthreads();

        const uint32_t sb = sbase + (t & 1) * STAGE_B;

        // ---- S = Q K^T (split) ----
        float s[8][4];
        #pragma unroll
        for (int j = 0; j < 8; j++)
            #pragma unroll
            for (int v = 0; v < 4; v++) s[j][v] = 0.0f;

        #pragma unroll
        for (int kt = 0; kt < 4; kt++) {
            #pragma unroll
            for (int j = 0; j < 8; j++) {
                uint32_t koff = (uint32_t)((8 * j + (lane & 7)) * AP +
                                           kt * 32 + ((lane >> 3) & 1) * 16);
                uint32_t kb[2], klr[2];
                ldmx2(kb,  sb + koff);
                ldmx2(klr, sb + MAT_B + koff);
                mma_bf16(s[j], qh[kt], kb);
                mma_bf16(s[j], qh[kt], klr);
                mma_bf16(s[j], ql[kt], kb);
            }
        }

        // ---- online softmax (rows r = lane>>2 and r+8) ----
        float mA = -CUDART_INF_F, mB = -CUDART_INF_F;
        #pragma unroll
        for (int j = 0; j < 8; j++) {
            mA = fmaxf(mA, fmaxf(s[j][0], s[j][1]));
            mB = fmaxf(mB, fmaxf(s[j][2], s[j][3]));
        }
        mA = fmaxf(mA, __shfl_xor_sync(0xffffffffu, mA, 1));
        mA = fmaxf(mA, __shfl_xor_sync(0xffffffffu, mA, 2));
        mB = fmaxf(mB, __shfl_xor_sync(0xffffffffu, mB, 1));
        mB = fmaxf(mB, __shfl_xor_sync(0xffffffffu, mB, 2));

        float mnA = fmaxf(miA, mA), mnB = fmaxf(miB, mB);
        float aA = exp_fma(miA - mnA), aB = exp_fma(miB - mnB);
        miA = mnA; miB = mnB;
        #pragma unroll
        for (int j = 0; j < 8; j++) {
            O[j][0] *= aA; O[j][1] *= aA;
            O[j][2] *= aB; O[j][3] *= aB;
        }

        float sumA = 0.0f, sumB = 0.0f;

        // ---- P·V (split), per k-step: exp + pack + 8 n-tiles of MMA ----
        #pragma unroll
        for (int kt = 0; kt < 4; kt++) {
            uint32_t ah4[4], al4[4];
            #pragma unroll
            for (int u = 0; u < 2; u++) {
                int jj = 2 * kt + u;
                float p0 = exp_fma(s[jj][0] - mnA);
                float p1 = exp_fma(s[jj][1] - mnA);
                float p2 = exp_fma(s[jj][2] - mnB);
                float p3 = exp_fma(s[jj][3] - mnB);
                sumA += p0 + p1; sumB += p2 + p3;
                __nv_bfloat162 hA = __floats2bfloat162_rn(p0, p1);
                __nv_bfloat162 hB = __floats2bfloat162_rn(p2, p3);
                float lA0 = p0 - __bfloat162float(hA.x);
                float lA1 = p1 - __bfloat162float(hA.y);
                float lB0 = p2 - __bfloat162float(hB.x);
                float lB1 = p3 - __bfloat162float(hB.y);
                ah4[0 + u * 2] = *(uint32_t*)&hA;
                ah4[1 + u * 2] = *(uint32_t*)&hB;
                al4[0 + u * 2] = pack_bf16(lA0, lA1);
                al4[1 + u * 2] = pack_bf16(lB0, lB1);
            }
            #pragma unroll
            for (int j = 0; j < 8; j++) {
                uint32_t voff = (uint32_t)((16 * kt + (lane & 15)) * AP + j * 16);
                uint32_t vb[2], vlr[2];
                ldmx2t(vb,  sb + 2 * MAT_B + voff);
                ldmx2t(vlr, sb + 3 * MAT_B + voff);
                mma_bf16(O[j], ah4, vb);
                mma_bf16(O[j], ah4, vlr);
                mma_bf16(O[j], al4, vb);
            }
        }

        sumA += __shfl_xor_sync(0xffffffffu, sumA, 1);
        sumA += __shfl_xor_sync(0xffffffffu, sumA, 2);
        sumB += __shfl_xor_sync(0xffffffffu, sumB, 1);
        sumB += __shfl_xor_sync(0xffffffffu, sumB, 2);
        liA = liA * aA + sumA;
        liB = liB * aB + sumB;

        __syncthreads();
    }

    // ---- epilogue ----
    float invA = 1.0f / liA, invB = 1.0f / liB;
    int rowA = m0 + wm + (lane >> 2);
    int rowB = rowA + 8;
    #pragma unroll
    for (int j = 0; j < 8; j++) {
        int col = 8 * j + 2 * (lane & 3);
        float2 oA; oA.x = O[j][0] * invA; oA.y = O[j][1] * invA;
        float2 oB; oB.x = O[j][2] * invB; oB.y = O[j][3] * invB;
        *(float2*)(g_ctx + hb + (size_t)rowA * HD + col) = oA;
        *(float2*)(g_ctx + hb + (size_t)rowB * HD + col) = oB;
    }
}

// ---------------------------------------------------------------------------
extern "C" void kernel_launch(void* const* d_in, const int* in_sizes, int n_in,
                              void* d_out, int out_size)
{
    const float* hid = (const float*)d_in[0];
    const float* rot = (const float*)d_in[1];
    const float* Wq  = (const float*)d_in[2];
    const float* Wk  = (const float*)d_in[3];
    const float* Wv  = (const float*)d_in[4];
    const float* Wo  = (const float*)d_in[5];
    const float* bo  = (const float*)d_in[6];
    float* out = (float*)d_out;

    cudaFuncSetAttribute(attn_hmma_kernel,
                         cudaFuncAttributeMaxDynamicSharedMemorySize, ATTN_SMEM);

    // 1) split inputs / weights into hi/lo bf16
    split_kernel<<<(MM * EE / 4 + 255) / 256, 256>>>(hid, 0, MM * EE / 4);
    split_kernel<<<(EE * EE / 4 + 255) / 256, 256>>>(Wq, 1, EE * EE / 4);
    split_kernel<<<(EE * EE / 4 + 255) / 256, 256>>>(Wk, 2, EE * EE / 4);
    split_kernel<<<(EE * EE / 4 + 255) / 256, 256>>>(Wv, 3, EE * EE / 4);
    split_kernel<<<(EE * EE / 4 + 255) / 256, 256>>>(Wo, 4, EE * EE / 4);

    // 2) QKV projections (HMMA)
    hmma_gemm_qkv_kernel<<<dim3(MM / 128, EE / 128, 3), 256>>>();

    // 3) RoPE + split q/k/v to hi/lo bf16
    int nrope = 3 * BH * TT * 16;
    rope_split_kernel<<<(nrope + 255) / 256, 256>>>(rot);

    // 4) Flash attention (HMMA, split-bf16, FMA-exp)
    attn_hmma_kernel<<<dim3(TT / 128, BH), 256, ATTN_SMEM>>>();

    // 5) gather + split ctx, output projection (HMMA)
    split_ctx_kernel<<<(MM * EE / 4 + 255) / 256, 256>>>();
    hmma_gemm_out_kernel<<<dim3(MM / 128, EE / 128), 256>>>(bo, out);
}

// round 5
// speedup vs baseline: 2.9965x; 1.2153x over previous
#include <cuda_runtime.h>
#include <cuda_bf16.h>
#include <math_constants.h>
#include <cstdint>

#define BB 2
#define TT 2048
#define EE 768
#define HH 12
#define HD 64
#define BH (BB*HH)
#define MM (BB*TT)
#define ROT 32
#define QSCALE 0.125f   // 64^-0.5

// ---------------------------------------------------------------------------
// Scratch
// ---------------------------------------------------------------------------
__device__ __nv_bfloat16 g_Xhi[MM * EE];
__device__ __nv_bfloat16 g_Xlo[MM * EE];
__device__ __nv_bfloat16 g_Wqhi[EE * EE];
__device__ __nv_bfloat16 g_Wqlo[EE * EE];
__device__ __nv_bfloat16 g_Wkhi[EE * EE];
__device__ __nv_bfloat16 g_Wklo[EE * EE];
__device__ __nv_bfloat16 g_Wvhi[EE * EE];
__device__ __nv_bfloat16 g_Wvlo[EE * EE];
__device__ __nv_bfloat16 g_Wohi[EE * EE];
__device__ __nv_bfloat16 g_Wolo[EE * EE];

// post-RoPE split q/k/v  [bh][t][d]
__device__ __nv_bfloat16 g_qhi[BH * TT * HD];
__device__ __nv_bfloat16 g_qlo[BH * TT * HD];
__device__ __nv_bfloat16 g_khi[BH * TT * HD];
__device__ __nv_bfloat16 g_klo[BH * TT * HD];
__device__ __nv_bfloat16 g_vhi[BH * TT * HD];
__device__ __nv_bfloat16 g_vlo[BH * TT * HD];

// attention output, split, [m][e] layout
__device__ __nv_bfloat16 g_Chi[MM * EE];
__device__ __nv_bfloat16 g_Clo[MM * EE];

// ---------------------------------------------------------------------------
// PTX helpers (baseline, compile for compute_103)
// ---------------------------------------------------------------------------
__device__ __forceinline__ uint32_t smem_u32(const void* p) {
    uint32_t a;
    asm("{ .reg .u64 t; cvta.to.shared.u64 t, %1; cvt.u32.u64 %0, t; }"
        : "=r"(a) : "l"(p));
    return a;
}
__device__ __forceinline__ void ldmx4(uint32_t* r, uint32_t addr) {
    asm volatile("ldmatrix.sync.aligned.m8n8.x4.shared.b16 {%0,%1,%2,%3}, [%4];"
                 : "=r"(r[0]), "=r"(r[1]), "=r"(r[2]), "=r"(r[3]) : "r"(addr));
}
__device__ __forceinline__ void ldmx2(uint32_t* r, uint32_t addr) {
    asm volatile("ldmatrix.sync.aligned.m8n8.x2.shared.b16 {%0,%1}, [%2];"
                 : "=r"(r[0]), "=r"(r[1]) : "r"(addr));
}
__device__ __forceinline__ void ldmx2t(uint32_t* r, uint32_t addr) {
    asm volatile("ldmatrix.sync.aligned.m8n8.x2.trans.shared.b16 {%0,%1}, [%2];"
                 : "=r"(r[0]), "=r"(r[1]) : "r"(addr));
}
__device__ __forceinline__ void mma_bf16(float* c, const uint32_t* a, const uint32_t* b) {
    asm volatile(
        "mma.sync.aligned.m16n8k16.row.col.f32.bf16.bf16.f32 "
        "{%0,%1,%2,%3}, {%4,%5,%6,%7}, {%8,%9}, {%0,%1,%2,%3};"
        : "+f"(c[0]), "+f"(c[1]), "+f"(c[2]), "+f"(c[3])
        : "r"(a[0]), "r"(a[1]), "r"(a[2]), "r"(a[3]), "r"(b[0]), "r"(b[1]));
}
__device__ __forceinline__ void cp16(uint32_t saddr, const void* g) {
    asm volatile("cp.async.cg.shared.global [%0], [%1], 16;" :: "r"(saddr), "l"(g));
}
#define CP_COMMIT() asm volatile("cp.async.commit_group;")
#define CP_WAIT1()  asm volatile("cp.async.wait_group 1;")

// MUFU-free exp (args <= 0, clamped at -87)
__device__ __forceinline__ float exp_fma(float x) {
    x = fmaxf(x, -87.0f);
    float t = x * 1.4426950408889634f;
    float r = t + 12582912.0f;
    float fi = r - 12582912.0f;
    float f = t - fi;
    float p = 1.3333558146428443e-3f;
    p = fmaf(p, f, 9.618129842071803e-3f);
    p = fmaf(p, f, 5.550410866482158e-2f);
    p = fmaf(p, f, 2.402265069591007e-1f);
    p = fmaf(p, f, 6.931471805599453e-1f);
    p = fmaf(p, f, 1.0f);
    int ii = __float_as_int(r) - 0x4B400000;
    float sc = __int_as_float((127 + ii) << 23);
    return p * sc;
}
__device__ __forceinline__ uint32_t pack_bf16(float a, float b) {
    __nv_bfloat162 h = __floats2bfloat162_rn(a, b);
    return *(uint32_t*)&h;
}
__device__ __forceinline__ uint32_t split_pair(float a, float b, uint32_t& lo) {
    __nv_bfloat162 h = __floats2bfloat162_rn(a, b);
    lo = pack_bf16(a - __bfloat162float(h.x), b - __bfloat162float(h.y));
    return *(uint32_t*)&h;
}

// ---------------------------------------------------------------------------
// merged split: X + Wq + Wk + Wv + Wo -> hi/lo bf16, one launch
// ---------------------------------------------------------------------------
#define NX4 (MM * EE / 4)
#define NW4 (EE * EE / 4)
#define NSPLIT (NX4 + 4 * NW4)

__global__ __launch_bounds__(256)
void split_all_kernel(const float* __restrict__ X,  const float* __restrict__ Wq,
                      const float* __restrict__ Wk, const float* __restrict__ Wv,
                      const float* __restrict__ Wo)
{
    int idx = blockIdx.x * blockDim.x + threadIdx.x;
    if (idx >= NSPLIT) return;
    const float* src; __nv_bfloat16 *hi, *lo; int i;
    if (idx < NX4) { src = X; hi = g_Xhi; lo = g_Xlo; i = idx; }
    else {
        int r = idx - NX4;
        int w = r / NW4; i = r - w * NW4;
        switch (w) {
            case 0: src = Wq; hi = g_Wqhi; lo = g_Wqlo; break;
            case 1: src = Wk; hi = g_Wkhi; lo = g_Wklo; break;
            case 2: src = Wv; hi = g_Wvhi; lo = g_Wvlo; break;
            default: src = Wo; hi = g_Wohi; lo = g_Wolo; break;
        }
    }
    float4 x = *(const float4*)(src + i * 4);
    float xs[4] = {x.x, x.y, x.z, x.w};
    __nv_bfloat16 h[4], l[4];
    #pragma unroll
    for (int j = 0; j < 4; j++) {
        h[j] = __float2bfloat16(xs[j]);
        l[j] = __float2bfloat16(xs[j] - __bfloat162float(h[j]));
    }
    *(uint2*)(hi + i * 4) = *(uint2*)h;
    *(uint2*)(lo + i * 4) = *(uint2*)l;
}

// ---------------------------------------------------------------------------
// HMMA GEMM mainloop, cp.async double-buffered.
// CTA tile 128x128, K chunk 32 (24 chunks). 8 warps: warp_m=(wid&1)*64,
// warp_n=(wid>>1)*32, warp tile 64x32.
// Dynamic smem: 2 stages x 4 matrices x (128 rows x 40 bf16 pitch) = 80 KB.
// ---------------------------------------------------------------------------
#define GP 40                     // pitch in bf16
#define GROWB 80                  // pitch in bytes
#define GMAT_B (128 * GROWB)      // 10240
#define GSTAGE_B (4 * GMAT_B)     // 40960
#define GEMM_SMEM (2 * GSTAGE_B)  // 81920

__device__ __forceinline__ void g_stage(uint32_t sb,
    const __nv_bfloat16* Ah, const __nv_bfloat16* Al,
    const __nv_bfloat16* Bh, const __nv_bfloat16* Bl,
    int m0, int n0, int k0, int tid)
{
    #pragma unroll
    for (int m = 0; m < 4; m++) {
        const __nv_bfloat16* src = (m == 0) ? Ah : (m == 1) ? Al : (m == 2) ? Bh : Bl;
        const int row0 = (m < 2) ? m0 : n0;
        #pragma unroll
        for (int it = 0; it < 2; it++) {
            int i = tid + it * 256;        // 0..511
            int r = i >> 2, c = (i & 3) * 16;   // byte col
            cp16(sb + (uint32_t)(m * GMAT_B + r * GROWB + c),
                 (const char*)(src + (size_t)(row0 + r) * EE + k0) + c);
        }
    }
}

__device__ __forceinline__ void gemm_mainloop(char* dsm,
    const __nv_bfloat16* __restrict__ Ah, const __nv_bfloat16* __restrict__ Al,
    const __nv_bfloat16* __restrict__ Bh, const __nv_bfloat16* __restrict__ Bl,
    int m0, int n0, float acc[4][4][4])
{
    const int tid  = threadIdx.x;
    const int wid  = tid >> 5;
    const int lane = tid & 31;
    const int warp_m = (wid & 1) * 64;
    const int warp_n = (wid >> 1) * 32;
    const uint32_t sbase = smem_u32(dsm);

    #pragma unroll
    for (int i = 0; i < 4; i++)
        #pragma unroll
        for (int j = 0; j < 4; j++)
            #pragma unroll
            for (int v = 0; v < 4; v++) acc[i][j][v] = 0.0f;

    g_stage(sbase, Ah, Al, Bh, Bl, m0, n0, 0, tid);
    CP_COMMIT();

    for (int chunk = 0; chunk < 24; chunk++) {
        if (chunk < 23)
            g_stage(sbase + ((chunk + 1) & 1) * GSTAGE_B,
                    Ah, Al, Bh, Bl, m0, n0, (chunk + 1) * 32, tid);
        CP_COMMIT();
        CP_WAIT1();
        __syncthreads();

        const uint32_t sb = sbase + (chunk & 1) * GSTAGE_B;
        #pragma unroll
        for (int ks = 0; ks < 2; ks++) {
            uint32_t ah[4][4], al[4][4];
            const int arow = warp_m + (lane & 15);
            const int acol = ks * 16 + (lane >> 4) * 8;
            #pragma unroll
            for (int i = 0; i < 4; i++) {
                uint32_t off = (uint32_t)(((arow + i * 16) * GP + acol) * 2);
                ldmx4(ah[i], sb + off);
                ldmx4(al[i], sb + GMAT_B + off);
            }
            const int brow = warp_n + (lane & 7);
            const int bcol = ks * 16 + ((lane >> 3) & 1) * 8;
            #pragma unroll
            for (int j = 0; j < 4; j++) {
                uint32_t boff = (uint32_t)(((brow + j * 8) * GP + bcol) * 2);
                uint32_t bh[2], bl[2];
                ldmx2(bh, sb + 2 * GMAT_B + boff);
                ldmx2(bl, sb + 3 * GMAT_B + boff);
                #pragma unroll
                for (int i = 0; i < 4; i++) {
                    mma_bf16(acc[i][j], ah[i], bh);
                    mma_bf16(acc[i][j], ah[i], bl);
                    mma_bf16(acc[i][j], al[i], bh);
                }
            }
        }
        __syncthreads();
    }
}

// ---------------------------------------------------------------------------
// QKV GEMM with fused RoPE + hi/lo split epilogue.
// z selects q/k/v. Writes [bh][t][d] bf16 hi/lo directly.
// ---------------------------------------------------------------------------
__global__ __launch_bounds__(256)
void hmma_gemm_qkv_kernel(const float* __restrict__ freqs)
{
    extern __shared__ char dsm[];
    const int which = blockIdx.z;
    const __nv_bfloat16 *Bh, *Bl;
    __nv_bfloat16 *dst_hi, *dst_lo;
    float scale;
    if (which == 0)      { Bh = g_Wqhi; Bl = g_Wqlo; dst_hi = g_qhi; dst_lo = g_qlo; scale = QSCALE; }
    else if (which == 1) { Bh = g_Wkhi; Bl = g_Wklo; dst_hi = g_khi; dst_lo = g_klo; scale = 1.0f; }
    else                 { Bh = g_Wvhi; Bl = g_Wvlo; dst_hi = g_vhi; dst_lo = g_vlo; scale = 1.0f; }

    const int m0 = blockIdx.x * 128;
    const int n0 = blockIdx.y * 128;
    float acc[4][4][4];
    gemm_mainloop(dsm, g_Xhi, g_Xlo, Bh, Bl, m0, n0, acc);

    const int wid  = threadIdx.x >> 5;
    const int lane = threadIdx.x & 31;
    const int warp_m = (wid & 1) * 64;
    const int warp_n = (wid >> 1) * 32;
    const int r0 = m0 + warp_m + (lane >> 2);
    const int c_local = (lane & 3) * 2;            // 0,2,4,6
    const int nwarp = n0 + warp_n;                 // multiple of 32
    const int head = nwarp >> 6;
    const int d_base = nwarp & 63;                 // 0 (rope half) or 32

    #pragma unroll
    for (int i = 0; i < 4; i++) {
        #pragma unroll
        for (int half = 0; half < 2; half++) {
            int row = r0 + i * 16 + half * 8;
            int b = row >> 11, t = row & (TT - 1);
            float vv[4][2];
            #pragma unroll
            for (int j = 0; j < 4; j++) {
                vv[j][0] = acc[i][j][half * 2 + 0] * scale;
                vv[j][1] = acc[i][j][half * 2 + 1] * scale;
            }
            if (d_base == 0) {
                const float* fr = freqs + t * ROT;
                #pragma unroll
                for (int ja = 0; ja < 2; ja++) {
                    #pragma unroll
                    for (int v2 = 0; v2 < 2; v2++) {
                        int da = c_local + ja * 8 + v2;   // [0,16)
                        float f1 = fr[da], f2 = fr[da + 16];
                        float x1 = vv[ja][v2], x2 = vv[ja + 2][v2];
                        vv[ja][v2]     = x1 * __cosf(f1) - x2 * __sinf(f1);
                        vv[ja + 2][v2] = x2 * __cosf(f2) + x1 * __sinf(f2);
                    }
                }
            }
            __nv_bfloat16* hi = dst_hi + (((size_t)(b * HH + head)) * TT + t) * HD;
            __nv_bfloat16* lo = dst_lo + (((size_t)(b * HH + head)) * TT + t) * HD;
            #pragma unroll
            for (int j = 0; j < 4; j++) {
                int d = d_base + c_local + j * 8;
                uint32_t lw, hw = split_pair(vv[j][0], vv[j][1], lw);
                *(uint32_t*)(hi + d) = hw;
                *(uint32_t*)(lo + d) = lw;
            }
        }
    }
}

// ---------------------------------------------------------------------------
// Output projection GEMM: reads g_Chi/g_Clo [m][768], writes out + bias.
// ---------------------------------------------------------------------------
__global__ __launch_bounds__(256)
void hmma_gemm_out_kernel(const float* __restrict__ bo, float* __restrict__ out)
{
    extern __shared__ char dsm[];
    const int m0 = blockIdx.x * 128;
    const int n0 = blockIdx.y * 128;
    float acc[4][4][4];
    gemm_mainloop(dsm, g_Chi, g_Clo, g_Wohi, g_Wolo, m0, n0, acc);

    const int wid  = threadIdx.x >> 5;
    const int lane = threadIdx.x & 31;
    const int r0 = m0 + (wid & 1) * 64 + (lane >> 2);
    const int c0 = n0 + (wid >> 1) * 32 + (lane & 3) * 2;
    #pragma unroll
    for (int i = 0; i < 4; i++) {
        #pragma unroll
        for (int j = 0; j < 4; j++) {
            int col = c0 + j * 8;
            #pragma unroll
            for (int half = 0; half < 2; half++) {
                int row = r0 + i * 16 + half * 8;
                float2 o;
                o.x = acc[i][j][half * 2 + 0] + bo[col];
                o.y = acc[i][j][half * 2 + 1] + bo[col + 1];
                *(float2*)(out + (size_t)row * EE + col) = o;
            }
        }
    }
}

// ---------------------------------------------------------------------------
// HMMA flash attention (as R3) with fused ctx hi/lo split epilogue.
// ---------------------------------------------------------------------------
#define AP 144
#define MAT_B (64 * AP)
#define STAGE_B (4 * MAT_B)
#define ATTN_SMEM (2 * STAGE_B)

__device__ __forceinline__ void stage_kv(uint32_t sb,
    const char* kh, const char* kl, const char* vh, const char* vl,
    int n0, int tid)
{
    #pragma unroll
    for (int m = 0; m < 4; m++) {
        const char* src = (m == 0) ? kh : (m == 1) ? kl : (m == 2) ? vh : vl;
        #pragma unroll
        for (int it = 0; it < 2; it++) {
            int i = tid + it * 256;
            int r = i >> 3, c = (i & 7) * 16;
            cp16(sb + (uint32_t)(m * MAT_B + r * AP + c),
                 src + (size_t)(n0 + r) * 128 + c);
        }
    }
}

__global__ __launch_bounds__(256)
void attn_hmma_kernel()
{
    extern __shared__ char dsm[];
    const int bh  = blockIdx.y;
    const int m0  = blockIdx.x * 128;
    const int tid = threadIdx.x;
    const int wid = tid >> 5, lane = tid & 31;
    const int wm  = wid * 16;

    const size_t hb = (size_t)bh * TT * HD;
    const char* qh_g = (const char*)(g_qhi + hb);
    const char* ql_g = (const char*)(g_qlo + hb);
    const char* kh_g = (const char*)(g_khi + hb);
    const char* kl_g = (const char*)(g_klo + hb);
    const char* vh_g = (const char*)(g_vhi + hb);
    const char* vl_g = (const char*)(g_vlo + hb);

    const uint32_t sbase = smem_u32(dsm);

    #pragma unroll
    for (int it = 0; it < 4; it++) {
        int i = tid + it * 256;
        int r = i >> 3, c = (i & 7) * 16;
        *(uint4*)(dsm + r * AP + c) =
            *(const uint4*)(qh_g + (size_t)(m0 + r) * 128 + c);
        *(uint4*)(dsm + 18432 + r * AP + c) =
            *(const uint4*)(ql_g + (size_t)(m0 + r) * 128 + c);
    }
    __syncthreads();

    uint32_t qh[4][4], ql[4][4];
    #pragma unroll
    for (int kt = 0; kt < 4; kt++) {
        uint32_t off = (uint32_t)((wm + (lane & 15)) * AP + kt * 32 + (lane >> 4) * 16);
        ldmx4(qh[kt], sbase + off);
        ldmx4(ql[kt], sbase + 18432 + off);
    }
    __syncthreads();

    float O[8][4];
    #pragma unroll
    for (int j = 0; j < 8; j++)
        #pragma unroll
        for (int v = 0; v < 4; v++) O[j][v] = 0.0f;
    float miA = -CUDART_INF_F, miB = -CUDART_INF_F;
    float liA = 0.0f, liB = 0.0f;

    stage_kv(sbase, kh_g, kl_g, vh_g, vl_g, 0, tid);
    CP_COMMIT();

    for (int t = 0; t < TT / 64; t++) {
        if (t + 1 < TT / 64)
            stage_kv(sbase + ((t + 1) & 1) * STAGE_B,
                     kh_g, kl_g, vh_g, vl_g, (t + 1) * 64, tid);
        CP_COMMIT();
        CP_WAIT1();
        __syncthreads();

        const uint32_t sb = sbase + (t & 1) * STAGE_B;

        float s[8][4];
        #pragma unroll
        for (int j = 0; j < 8; j++)
            #pragma unroll
            for (int v = 0; v < 4; v++) s[j][v] = 0.0f;

        #pragma unroll
        for (int kt = 0; kt < 4; kt++) {
            #pragma unroll
            for (int j = 0; j < 8; j++) {
                uint32_t koff = (uint32_t)((8 * j + (lane & 7)) * AP +
                                           kt * 32 + ((lane >> 3) & 1) * 16);
                uint32_t kb[2], klr[2];
                ldmx2(kb,  sb + koff);
                ldmx2(klr, sb + MAT_B + koff);
                mma_bf16(s[j], qh[kt], kb);
                mma_bf16(s[j], qh[kt], klr);
                mma_bf16(s[j], ql[kt], kb);
            }
        }

        float mA = -CUDART_INF_F, mB = -CUDART_INF_F;
        #pragma unroll
        for (int j = 0; j < 8; j++) {
            mA = fmaxf(mA, fmaxf(s[j][0], s[j][1]));
            mB = fmaxf(mB, fmaxf(s[j][2], s[j][3]));
        }
        mA = fmaxf(mA, __shfl_xor_sync(0xffffffffu, mA, 1));
        mA = fmaxf(mA, __shfl_xor_sync(0xffffffffu, mA, 2));
        mB = fmaxf(mB, __shfl_xor_sync(0xffffffffu, mB, 1));
        mB = fmaxf(mB, __shfl_xor_sync(0xffffffffu, mB, 2));

        float mnA = fmaxf(miA, mA), mnB = fmaxf(miB, mB);
        float aA = exp_fma(miA - mnA), aB = exp_fma(miB - mnB);
        miA = mnA; miB = mnB;
        #pragma unroll
        for (int j = 0; j < 8; j++) {
            O[j][0] *= aA; O[j][1] *= aA;
            O[j][2] *= aB; O[j][3] *= aB;
        }

        float sumA = 0.0f, sumB = 0.0f;

        #pragma unroll
        for (int kt = 0; kt < 4; kt++) {
            uint32_t ah4[4], al4[4];
            #pragma unroll
            for (int u = 0; u < 2; u++) {
                int jj = 2 * kt + u;
                float p0 = exp_fma(s[jj][0] - mnA);
                float p1 = exp_fma(s[jj][1] - mnA);
                float p2 = exp_fma(s[jj][2] - mnB);
                float p3 = exp_fma(s[jj][3] - mnB);
                sumA += p0 + p1; sumB += p2 + p3;
                uint32_t lA, lB;
                ah4[0 + u * 2] = split_pair(p0, p1, lA);
                ah4[1 + u * 2] = split_pair(p2, p3, lB);
                al4[0 + u * 2] = lA;
                al4[1 + u * 2] = lB;
            }
            #pragma unroll
            for (int j = 0; j < 8; j++) {
                uint32_t voff = (uint32_t)((16 * kt + (lane & 15)) * AP + j * 16);
                uint32_t vb[2], vlr[2];
                ldmx2t(vb,  sb + 2 * MAT_B + voff);
                ldmx2t(vlr, sb + 3 * MAT_B + voff);
                mma_bf16(O[j], ah4, vb);
                mma_bf16(O[j], ah4, vlr);
                mma_bf16(O[j], al4, vb);
            }
        }

        sumA += __shfl_xor_sync(0xffffffffu, sumA, 1);
        sumA += __shfl_xor_sync(0xffffffffu, sumA, 2);
        sumB += __shfl_xor_sync(0xffffffffu, sumB, 1);
        sumB += __shfl_xor_sync(0xffffffffu, sumB, 2);
        liA = liA * aA + sumA;
        liB = liB * aB + sumB;

        __syncthreads();
    }

    // ---- epilogue: normalize + hi/lo split, write [m][e] layout ----
    float invA = 1.0f / liA, invB = 1.0f / liB;
    int tA = m0 + wm + (lane >> 2);
    int tB = tA + 8;
    int b = bh / HH, h = bh % HH;
    size_t rowA_base = (size_t)(b * TT + tA) * EE + h * HD;
    size_t rowB_base = (size_t)(b * TT + tB) * EE + h * HD;
    #pragma unroll
    for (int j = 0; j < 8; j++) {
        int col = 8 * j + 2 * (lane & 3);
        uint32_t lA, hA = split_pair(O[j][0] * invA, O[j][1] * invA, lA);
        uint32_t lB, hB = split_pair(O[j][2] * invB, O[j][3] * invB, lB);
        *(uint32_t*)(g_Chi + rowA_base + col) = hA;
        *(uint32_t*)(g_Clo + rowA_base + col) = lA;
        *(uint32_t*)(g_Chi + rowB_base + col) = hB;
        *(uint32_t*)(g_Clo + rowB_base + col) = lB;
    }
}

// ---------------------------------------------------------------------------
extern "C" void kernel_launch(void* const* d_in, const int* in_sizes, int n_in,
                              void* d_out, int out_size)
{
    const float* hid = (const float*)d_in[0];
    const float* rot = (const float*)d_in[1];
    const float* Wq  = (const float*)d_in[2];
    const float* Wk  = (const float*)d_in[3];
    const float* Wv  = (const float*)d_in[4];
    const float* Wo  = (const float*)d_in[5];
    const float* bo  = (const float*)d_in[6];
    float* out = (float*)d_out;

    cudaFuncSetAttribute(attn_hmma_kernel,
                         cudaFuncAttributeMaxDynamicSharedMemorySize, ATTN_SMEM);
    cudaFuncSetAttribute(hmma_gemm_qkv_kernel,
                         cudaFuncAttributeMaxDynamicSharedMemorySize, GEMM_SMEM);
    cudaFuncSetAttribute(hmma_gemm_out_kernel,
                         cudaFuncAttributeMaxDynamicSharedMemorySize, GEMM_SMEM);

    // 1) split X + all weights (one launch)
    split_all_kernel<<<(NSPLIT + 255) / 256, 256>>>(hid, Wq, Wk, Wv, Wo);

    // 2) QKV projections + fused RoPE + split (HMMA, pipelined)
    hmma_gemm_qkv_kernel<<<dim3(MM / 128, EE / 128, 3), 256, GEMM_SMEM>>>(rot);

    // 3) Flash attention (HMMA) + fused ctx split
    attn_hmma_kernel<<<dim3(TT / 128, BH), 256, ATTN_SMEM>>>();

    // 4) Output projection + bias (HMMA, pipelined)
    hmma_gemm_out_kernel<<<dim3(MM / 128, EE / 128), 256, GEMM_SMEM>>>(bo, out);
}